// round 1
// baseline (speedup 1.0000x reference)
#include <cuda_runtime.h>
#include <cuda_bf16.h>

// Problem constants
#define BB 8
#define CC 256
#define HH 64
#define WW 64
#define OO 256
#define KK2 9
#define PLANE (HH * WW)   // 4096

// Pre-transposed weight: wT[c][k][o]  (c*2304 + k*256 + o)
__device__ float g_wT[CC * KK2 * OO];

__global__ void transpose_w_kernel(const float* __restrict__ w) {
    int n = blockIdx.x * blockDim.x + threadIdx.x;   // over O*C*K2 = 589824
    if (n >= OO * CC * KK2) return;
    int o = n / (CC * KK2);
    int r = n % (CC * KK2);
    int c = r / KK2;
    int k = r % KK2;
    g_wT[(c * KK2 + k) * OO + o] = w[n];
}

__global__ __launch_bounds__(256, 2)
void dcn_kernel(const float* __restrict__ x,
                const float* __restrict__ offset,
                float* __restrict__ out) {
    const int h   = blockIdx.x;          // output row
    const int b   = blockIdx.y;          // batch
    const int tid = threadIdx.x;
    const int to  = tid >> 4;            // 0..15 : o-subtile (16 o's each)
    const int tp  = tid & 15;            // 0..15 : p-subtile (4 px each)

    __shared__ int4   sidx[KK2 * WW];    // 576 * 16B
    __shared__ float4 swgt[KK2 * WW];    // 576 * 16B
    __shared__ float  S[KK2 * WW];       // 576 floats, [k*64 + p]
    __shared__ float  wsh[KK2 * OO];     // 2304 floats, [k*256 + o]

    // ---- Precompute bilinear gather indices+weights, shared across all c ----
    for (int i = tid; i < KK2 * WW; i += 256) {
        int k = i >> 6;                  // 0..8
        int p = i & 63;                  // 0..63
        int ky = k / 3, kx = k % 3;
        const float dy = offset[(((b * 2 * KK2 + 2 * k    ) * HH + h) * WW) + p];
        const float dx = offset[(((b * 2 * KK2 + 2 * k + 1) * HH + h) * WW) + p];
        float py = (float)(h - 1 + ky) + dy;
        float px = (float)(p - 1 + kx) + dx;
        float y0f = floorf(py), x0f = floorf(px);
        float fy = py - y0f,    fx = px - x0f;
        int iy0 = (int)y0f, ix0 = (int)x0f;
        int iy1 = iy0 + 1,  ix1 = ix0 + 1;
        bool vy0 = (iy0 >= 0) && (iy0 < HH);
        bool vy1 = (iy1 >= 0) && (iy1 < HH);
        bool vx0 = (ix0 >= 0) && (ix0 < WW);
        bool vx1 = (ix1 >= 0) && (ix1 < WW);
        float w00 = (1.f - fy) * (1.f - fx);
        float w01 = (1.f - fy) * fx;
        float w10 = fy * (1.f - fx);
        float w11 = fy * fx;
        int4   id;
        float4 wg;
        id.x = (vy0 && vx0) ? (iy0 * WW + ix0) : 0;  wg.x = (vy0 && vx0) ? w00 : 0.f;
        id.y = (vy0 && vx1) ? (iy0 * WW + ix1) : 0;  wg.y = (vy0 && vx1) ? w01 : 0.f;
        id.z = (vy1 && vx0) ? (iy1 * WW + ix0) : 0;  wg.z = (vy1 && vx0) ? w10 : 0.f;
        id.w = (vy1 && vx1) ? (iy1 * WW + ix1) : 0;  wg.w = (vy1 && vx1) ? w11 : 0.f;
        sidx[i] = id;
        swgt[i] = wg;
    }

    float4 acc[16];
#pragma unroll
    for (int i = 0; i < 16; i++) acc[i] = make_float4(0.f, 0.f, 0.f, 0.f);

    const float* xb = x + (size_t)b * CC * PLANE;

    for (int c = 0; c < CC; c++) {
        __syncthreads();   // previous iteration finished reading S / wsh

        // Stage weights for this c: fully coalesced from pre-transposed wT
        const float* wp = g_wT + c * (KK2 * OO);
#pragma unroll
        for (int j = 0; j < KK2; j++)
            wsh[j * 256 + tid] = wp[j * 256 + tid];

        // Sample S[k][p] via precomputed bilinear taps (clamped idx, zeroed wgt)
        const float* xp = xb + c * PLANE;
        for (int i = tid; i < KK2 * WW; i += 256) {
            int4   id = sidx[i];
            float4 wg = swgt[i];
            float v = wg.x * __ldg(xp + id.x)
                    + wg.y * __ldg(xp + id.y)
                    + wg.z * __ldg(xp + id.z)
                    + wg.w * __ldg(xp + id.w);
            S[i] = v;
        }
        __syncthreads();

        // Rank-1 update accumulation: 9 taps, 64 FMA per tap per thread
        const float4* S4 = (const float4*)S;
#pragma unroll
        for (int k = 0; k < KK2; k++) {
            float4 s = S4[k * 16 + tp];
            const float4* wr = (const float4*)(wsh + k * 256 + to * 16);
#pragma unroll
            for (int i = 0; i < 4; i++) {
                float4 w = wr[i];
                acc[4*i+0].x += w.x * s.x; acc[4*i+0].y += w.x * s.y;
                acc[4*i+0].z += w.x * s.z; acc[4*i+0].w += w.x * s.w;
                acc[4*i+1].x += w.y * s.x; acc[4*i+1].y += w.y * s.y;
                acc[4*i+1].z += w.y * s.z; acc[4*i+1].w += w.y * s.w;
                acc[4*i+2].x += w.z * s.x; acc[4*i+2].y += w.z * s.y;
                acc[4*i+2].z += w.z * s.z; acc[4*i+2].w += w.z * s.w;
                acc[4*i+3].x += w.w * s.x; acc[4*i+3].y += w.w * s.y;
                acc[4*i+3].z += w.w * s.z; acc[4*i+3].w += w.w * s.w;
            }
        }
    }

    // ---- Epilogue: out[b][o][h][w], w = tp*4..tp*4+3 contiguous -> float4 ----
#pragma unroll
    for (int j = 0; j < 16; j++) {
        int o = to * 16 + j;
        float* op = out + ((((size_t)b * OO + o) * HH + h) * WW) + tp * 4;
        *(float4*)op = acc[j];
    }
}

extern "C" void kernel_launch(void* const* d_in, const int* in_sizes, int n_in,
                              void* d_out, int out_size) {
    const float* x      = (const float*)d_in[0];   // [8,256,64,64]
    const float* offset = (const float*)d_in[1];   // [8,18,64,64]
    const float* weight = (const float*)d_in[2];   // [256,256,3,3]
    float* out = (float*)d_out;                    // [8,256,64,64]

    // Pre-transpose weight into [c][k][o] for coalesced per-c staging
    int nw = OO * CC * KK2;
    transpose_w_kernel<<<(nw + 255) / 256, 256>>>(weight);

    dim3 grid(HH, BB);   // (h, b)
    dcn_kernel<<<grid, 256>>>(x, offset, out);
}

// round 2
// speedup vs baseline: 1.1789x; 1.1789x over previous
#include <cuda_runtime.h>
#include <cuda_bf16.h>

#define BB 8
#define CC 256
#define HH 64
#define WW 64
#define OO 256
#define KK2 9
#define PLANE (HH * WW)   // 4096
#define NS (KK2 * WW)     // 576 sample slots per row
#define NW4 (KK2 * OO / 4) // 576 float4 weight slots per c

// Pre-transposed weight: wT[c][k][o]  (c*2304 + k*256 + o)
__device__ float g_wT[CC * KK2 * OO];

__global__ void transpose_w_kernel(const float* __restrict__ w) {
    int n = blockIdx.x * blockDim.x + threadIdx.x;   // over O*C*K2 = 589824
    if (n >= OO * CC * KK2) return;
    int o = n / (CC * KK2);
    int r = n % (CC * KK2);
    int c = r / KK2;
    int k = r % KK2;
    g_wT[(c * KK2 + k) * OO + o] = w[n];
}

__global__ __launch_bounds__(256, 2)
void dcn_kernel(const float* __restrict__ x,
                const float* __restrict__ offset,
                float* __restrict__ out) {
    const int h   = blockIdx.x;          // output row
    const int b   = blockIdx.y;          // batch
    const int tid = threadIdx.x;
    const int to  = tid >> 4;            // 0..15 : o-subtile (16 o's each)
    const int tp  = tid & 15;            // 0..15 : p-subtile (4 px each)

    __shared__ int4   sidx[NS];          // bilinear tap indices (clamped)
    __shared__ float4 swgt[NS];          // bilinear tap weights (zeroed if OOB)
    __shared__ float  S[2][NS];          // double-buffered sampled values
    __shared__ float4 W4[2][NW4];        // double-buffered weights [k*64 + o/4]

    // ---- Precompute bilinear gather indices+weights, shared across all c ----
    for (int i = tid; i < NS; i += 256) {
        int k = i >> 6;                  // 0..8
        int p = i & 63;                  // 0..63
        int ky = k / 3, kx = k % 3;
        const float dy = offset[(((b * 2 * KK2 + 2 * k    ) * HH + h) * WW) + p];
        const float dx = offset[(((b * 2 * KK2 + 2 * k + 1) * HH + h) * WW) + p];
        float py = (float)(h - 1 + ky) + dy;
        float px = (float)(p - 1 + kx) + dx;
        float y0f = floorf(py), x0f = floorf(px);
        float fy = py - y0f,    fx = px - x0f;
        int iy0 = (int)y0f, ix0 = (int)x0f;
        int iy1 = iy0 + 1,  ix1 = ix0 + 1;
        bool vy0 = (iy0 >= 0) && (iy0 < HH);
        bool vy1 = (iy1 >= 0) && (iy1 < HH);
        bool vx0 = (ix0 >= 0) && (ix0 < WW);
        bool vx1 = (ix1 >= 0) && (ix1 < WW);
        float w00 = (1.f - fy) * (1.f - fx);
        float w01 = (1.f - fy) * fx;
        float w10 = fy * (1.f - fx);
        float w11 = fy * fx;
        int4   id;
        float4 wg;
        id.x = (vy0 && vx0) ? (iy0 * WW + ix0) : 0;  wg.x = (vy0 && vx0) ? w00 : 0.f;
        id.y = (vy0 && vx1) ? (iy0 * WW + ix1) : 0;  wg.y = (vy0 && vx1) ? w01 : 0.f;
        id.z = (vy1 && vx0) ? (iy1 * WW + ix0) : 0;  wg.z = (vy1 && vx0) ? w10 : 0.f;
        id.w = (vy1 && vx1) ? (iy1 * WW + ix1) : 0;  wg.w = (vy1 && vx1) ? w11 : 0.f;
        sidx[i] = id;
        swgt[i] = wg;
    }

    float4 acc[16];
#pragma unroll
    for (int i = 0; i < 16; i++) acc[i] = make_float4(0.f, 0.f, 0.f, 0.f);

    const float*  xb  = x + (size_t)b * CC * PLANE;
    const float4* wT4 = (const float4*)g_wT;

    // Per-thread prefetch registers: up to 3 slots (tid<64 owns 3, else 2)
    float4 rW[3];
    float  rs[3][4];
    const bool has3 = (tid < NS - 512);   // tid < 64

    __syncthreads();   // sidx/swgt ready before first prefetch reads them

    // ---- Prefetch c = 0 (raw taps + weights) ----
    {
        const float4* wp = wT4 + 0 * NW4;
        const float*  xp = xb;
#pragma unroll
        for (int j = 0; j < 3; j++) {
            int i = tid + j * 256;
            if (j < 2 || has3) {
                rW[j] = wp[i];
                int4 id = sidx[i];
                rs[j][0] = __ldg(xp + id.x);
                rs[j][1] = __ldg(xp + id.y);
                rs[j][2] = __ldg(xp + id.z);
                rs[j][3] = __ldg(xp + id.w);
            }
        }
    }

    int cur = 0;
    for (int c = 0; c < CC; c++) {
        // ---- Stage prefetched data into smem buffer 'cur' ----
#pragma unroll
        for (int j = 0; j < 3; j++) {
            int i = tid + j * 256;
            if (j < 2 || has3) {
                W4[cur][i] = rW[j];
                float4 wg = swgt[i];
                S[cur][i] = wg.x * rs[j][0] + wg.y * rs[j][1]
                          + wg.z * rs[j][2] + wg.w * rs[j][3];
            }
        }
        __syncthreads();

        // ---- Issue prefetch LDGs for c+1 (consumed next iteration) ----
        if (c + 1 < CC) {
            const float4* wp = wT4 + (c + 1) * NW4;
            const float*  xp = xb + (c + 1) * PLANE;
#pragma unroll
            for (int j = 0; j < 3; j++) {
                int i = tid + j * 256;
                if (j < 2 || has3) {
                    rW[j] = wp[i];
                    int4 id = sidx[i];
                    rs[j][0] = __ldg(xp + id.x);
                    rs[j][1] = __ldg(xp + id.y);
                    rs[j][2] = __ldg(xp + id.z);
                    rs[j][3] = __ldg(xp + id.w);
                }
            }
        }

        // ---- Rank-1 update: 9 taps, 64 FMA per tap per thread ----
        const float4* S4 = (const float4*)S[cur];
        const float4* Wc = W4[cur];
#pragma unroll
        for (int k = 0; k < KK2; k++) {
            float4 s = S4[k * 16 + tp];
            const float4* wr = Wc + k * 64 + to * 4;
#pragma unroll
            for (int i = 0; i < 4; i++) {
                float4 w = wr[i];
                acc[4*i+0].x += w.x * s.x; acc[4*i+0].y += w.x * s.y;
                acc[4*i+0].z += w.x * s.z; acc[4*i+0].w += w.x * s.w;
                acc[4*i+1].x += w.y * s.x; acc[4*i+1].y += w.y * s.y;
                acc[4*i+1].z += w.y * s.z; acc[4*i+1].w += w.y * s.w;
                acc[4*i+2].x += w.z * s.x; acc[4*i+2].y += w.z * s.y;
                acc[4*i+2].z += w.z * s.z; acc[4*i+2].w += w.z * s.w;
                acc[4*i+3].x += w.w * s.x; acc[4*i+3].y += w.w * s.y;
                acc[4*i+3].z += w.w * s.z; acc[4*i+3].w += w.w * s.w;
            }
        }
        cur ^= 1;
    }

    // ---- Epilogue: out[b][o][h][w], w = tp*4..tp*4+3 contiguous -> float4 ----
#pragma unroll
    for (int j = 0; j < 16; j++) {
        int o = to * 16 + j;
        float* op = out + ((((size_t)b * OO + o) * HH + h) * WW) + tp * 4;
        *(float4*)op = acc[j];
    }
}

extern "C" void kernel_launch(void* const* d_in, const int* in_sizes, int n_in,
                              void* d_out, int out_size) {
    const float* x      = (const float*)d_in[0];   // [8,256,64,64]
    const float* offset = (const float*)d_in[1];   // [8,18,64,64]
    const float* weight = (const float*)d_in[2];   // [256,256,3,3]
    float* out = (float*)d_out;                    // [8,256,64,64]

    int nw = OO * CC * KK2;
    transpose_w_kernel<<<(nw + 255) / 256, 256>>>(weight);

    dim3 grid(HH, BB);   // (h, b)
    dcn_kernel<<<grid, 256>>>(x, offset, out);
}